// round 1
// baseline (speedup 1.0000x reference)
#include <cuda_runtime.h>
#include <math.h>
#include <stdint.h>

#define HD 32
#define MAXN 10000

// Scratch (device globals — no allocation allowed)
__device__ float g_z[MAXN * HD];
__device__ float g_u[MAXN * HD];
__device__ float g_v[MAXN * HD];
__device__ float g_m[MAXN * HD];
__device__ float g_pa[MAXN];
__device__ float g_pb[MAXN];
__device__ float g_hsum[HD];

// fp32 atomic max via sign-aware integer atomics (exact)
__device__ __forceinline__ void atomicMaxF(float* addr, float v) {
    if (v >= 0.0f) atomicMax((int*)addr, __float_as_int(v));
    else           atomicMin((unsigned int*)addr, __float_as_uint(v));
}

// ---------------------------------------------------------------------------
// Fill p with -1e9 (the 400MB HBM-bound floor)
// ---------------------------------------------------------------------------
__global__ void k_fill4(float4* __restrict__ p, size_t n4) {
    size_t i = (size_t)blockIdx.x * blockDim.x + threadIdx.x;
    size_t stride = (size_t)gridDim.x * blockDim.x;
    const float4 val = make_float4(-1e9f, -1e9f, -1e9f, -1e9f);
    for (; i < n4; i += stride) p[i] = val;
}
__global__ void k_fill1(float* __restrict__ p, size_t n) {
    size_t i = (size_t)blockIdx.x * blockDim.x + threadIdx.x;
    size_t stride = (size_t)gridDim.x * blockDim.x;
    for (; i < n; i += stride) p[i] = -1e9f;
}

// ---------------------------------------------------------------------------
// Encoder: z = [x,h]@W_enc + b_enc; precompute u = z@W_msg[0:32], v = z@W_msg[32:64];
// init m = -inf; zero hsum. Warp per node, lane = feature.
// ---------------------------------------------------------------------------
__global__ void k_encoder(const float* __restrict__ x, const float* __restrict__ h,
                          const float* __restrict__ W_enc, const float* __restrict__ b_enc,
                          const float* __restrict__ W_msg, int N) {
    __shared__ float sWe[33 * HD];
    __shared__ float sWm[64 * HD];
    int tid = threadIdx.x;
    for (int i = tid; i < 33 * HD; i += blockDim.x) sWe[i] = W_enc[i];
    for (int i = tid; i < 64 * HD; i += blockDim.x) sWm[i] = W_msg[i];
    if (blockIdx.x == 0 && tid < HD) g_hsum[tid] = 0.0f;
    __syncthreads();

    int lane = tid & 31;
    int node = (int)((blockIdx.x * (size_t)blockDim.x + tid) >> 5);
    if (node >= N) return;

    float xn = x[node];
    float hl = h[node * HD + lane];
    float z = fmaf(xn, sWe[lane], b_enc[lane]);
#pragma unroll
    for (int k = 0; k < HD; k++) {
        float hk = __shfl_sync(0xffffffffu, hl, k);
        z = fmaf(hk, sWe[(1 + k) * HD + lane], z);
    }
    g_z[node * HD + lane] = z;
    g_m[node * HD + lane] = __int_as_float(0xFF800000);  // -inf

    float u = 0.0f, v = 0.0f;
#pragma unroll
    for (int k = 0; k < HD; k++) {
        float zk = __shfl_sync(0xffffffffu, z, k);
        u = fmaf(zk, sWm[k * HD + lane], u);
        v = fmaf(zk, sWm[(HD + k) * HD + lane], v);
    }
    g_u[node * HD + lane] = u;
    g_v[node * HD + lane] = v;
}

// ---------------------------------------------------------------------------
// Per-edge messages + scatter-max. Warp per edge, lane = feature.
// msg = u[d] + v[s] + w*W_msg[64,:] + b_msg
// ---------------------------------------------------------------------------
__global__ void k_msg(const int* __restrict__ dests, const int* __restrict__ sources,
                      const float* __restrict__ weights,
                      const float* __restrict__ W_msg, const float* __restrict__ b_msg, int E) {
    int tid = threadIdx.x;
    int lane = tid & 31;
    int e = (int)((blockIdx.x * (size_t)blockDim.x + tid) >> 5);
    if (e >= E) return;
    float cw = W_msg[64 * HD + lane];
    float bm = b_msg[lane];
    int d = dests[e], s = sources[e];
    float w = weights[e];
    float msg = g_u[d * HD + lane] + g_v[s * HD + lane] + fmaf(w, cw, bm);
    atomicMaxF(&g_m[d * HD + lane], msg);
}

// ---------------------------------------------------------------------------
// Update + decode + pred-scalar precompute + hsum accumulation.
// Warp per node, lane = feature.
// ---------------------------------------------------------------------------
__global__ void k_update(const float* __restrict__ W_upd, const float* __restrict__ b_upd,
                         const float* __restrict__ W_dec, const float* __restrict__ b_dec,
                         const float* __restrict__ W_pred,
                         float* __restrict__ out_y, float* __restrict__ out_h, int N) {
    __shared__ float sWu[64 * HD];
    __shared__ float red[8][HD];
    int tid = threadIdx.x;
    for (int i = tid; i < 64 * HD; i += blockDim.x) sWu[i] = W_upd[i];
    __syncthreads();

    int lane = tid & 31;
    int wip = tid >> 5;
    int node = (int)((blockIdx.x * (size_t)blockDim.x + tid) >> 5);
    bool act = node < N;
    float hn = 0.0f;

    if (act) {
        float z = g_z[node * HD + lane];
        float m = g_m[node * HD + lane];
        if (isinf(m) && m < 0.0f) m = 0.0f;  // no incoming edge -> 0
        hn = b_upd[lane];
#pragma unroll
        for (int k = 0; k < HD; k++) {
            float zk = __shfl_sync(0xffffffffu, z, k);
            hn = fmaf(zk, sWu[k * HD + lane], hn);
        }
#pragma unroll
        for (int k = 0; k < HD; k++) {
            float mk = __shfl_sync(0xffffffffu, m, k);
            hn = fmaf(mk, sWu[(HD + k) * HD + lane], hn);
        }
        out_h[node * HD + lane] = hn;

        // y = [z, h_new] @ W_dec + b_dec  (warp reduce)
        float ry = fmaf(z, W_dec[lane], hn * W_dec[HD + lane]);
        // pred per-node scalars
        float ra = hn * W_pred[lane];
        float rb = hn * W_pred[HD + lane];
#pragma unroll
        for (int o = 16; o > 0; o >>= 1) {
            ry += __shfl_xor_sync(0xffffffffu, ry, o);
            ra += __shfl_xor_sync(0xffffffffu, ra, o);
            rb += __shfl_xor_sync(0xffffffffu, rb, o);
        }
        if (lane == 0) {
            out_y[node] = ry + b_dec[0];
            g_pa[node] = ra;
            g_pb[node] = rb;
        }
    }

    // block-level partial sum of h_new for termination head
    red[wip][lane] = act ? hn : 0.0f;
    __syncthreads();
    if (wip == 0) {
        float s = red[0][lane];
#pragma unroll
        for (int j = 1; j < 8; j++) s += red[j][lane];
        atomicAdd(&g_hsum[lane], s);
    }
}

// ---------------------------------------------------------------------------
// Termination scalar: t = (mean(h_new) @ W_term + b_term)
// ---------------------------------------------------------------------------
__global__ void k_t(const float* __restrict__ W_term, const float* __restrict__ b_term,
                    float* __restrict__ out_t, int N) {
    int lane = threadIdx.x;
    float v = (g_hsum[lane] / (float)N) * W_term[lane];
#pragma unroll
    for (int o = 16; o > 0; o >>= 1) v += __shfl_xor_sync(0xffffffffu, v, o);
    if (lane == 0) out_t[0] = v + b_term[0];
}

// ---------------------------------------------------------------------------
// Predecessor edge scores scattered into p. Thread per edge.
// ---------------------------------------------------------------------------
__global__ void k_pred(const int* __restrict__ dests, const int* __restrict__ sources,
                       const float* __restrict__ weights,
                       const float* __restrict__ W_pred, const float* __restrict__ b_pred,
                       float* __restrict__ p, int N, int E) {
    int e = blockIdx.x * blockDim.x + threadIdx.x;
    if (e >= E) return;
    int d = dests[e], s = sources[e];
    float sc = g_pa[d] + g_pb[s] + fmaf(weights[e], W_pred[64], b_pred[0]);
    p[(size_t)d * N + s] = sc;
}

// ---------------------------------------------------------------------------
extern "C" void kernel_launch(void* const* d_in, const int* in_sizes, int n_in,
                              void* d_out, int out_size) {
    const int*   sources = (const int*)d_in[0];
    const int*   dests   = (const int*)d_in[1];
    const float* weights = (const float*)d_in[2];
    const float* x       = (const float*)d_in[3];
    const float* h       = (const float*)d_in[4];
    const float* W_enc   = (const float*)d_in[5];
    const float* b_enc   = (const float*)d_in[6];
    const float* W_msg   = (const float*)d_in[7];
    const float* b_msg   = (const float*)d_in[8];
    const float* W_upd   = (const float*)d_in[9];
    const float* b_upd   = (const float*)d_in[10];
    const float* W_dec   = (const float*)d_in[11];
    const float* b_dec   = (const float*)d_in[12];
    const float* W_term  = (const float*)d_in[13];
    const float* b_term  = (const float*)d_in[14];
    const float* W_pred  = (const float*)d_in[15];
    const float* b_pred  = (const float*)d_in[16];

    int E = in_sizes[0];
    int N = in_sizes[3];  // x is (N, 1)

    float* out   = (float*)d_out;
    float* out_y = out;
    float* out_p = out + N;
    float* out_h = out + N + (size_t)N * N;
    float* out_t = out_h + (size_t)N * HD;

    size_t nn = (size_t)N * N;
    if ((((uintptr_t)out_p) & 15) == 0 && (nn & 3) == 0) {
        k_fill4<<<4096, 256>>>((float4*)out_p, nn / 4);
    } else {
        k_fill1<<<4096, 256>>>(out_p, nn);
    }

    int nodeBlocks = (N + 7) / 8;          // 8 warps/block, warp per node
    int edgeWarpBlocks = (E + 7) / 8;      // warp per edge
    k_encoder<<<nodeBlocks, 256>>>(x, h, W_enc, b_enc, W_msg, N);
    k_msg<<<edgeWarpBlocks, 256>>>(dests, sources, weights, W_msg, b_msg, E);
    k_update<<<nodeBlocks, 256>>>(W_upd, b_upd, W_dec, b_dec, W_pred, out_y, out_h, N);
    k_t<<<1, 32>>>(W_term, b_term, out_t, N);
    k_pred<<<(E + 255) / 256, 256>>>(dests, sources, weights, W_pred, b_pred, out_p, N, E);
}